// round 2
// baseline (speedup 1.0000x reference)
#include <cuda_runtime.h>
#include <stdint.h>

// ExtractSearchWindows: out[b,y,x, wy*7+wx, ty*7+tx] = Qpad[b][y+wy+ty][x+wx+tx]
// where Qpad = zero-padded (pad=6) image, values = trunc(input) in [0,255).
// Output dtype: float32 (harness materializes the uint8 reference as f32).
//
// 708 MB of f32 stores, 294 KB input -> pure store-BW problem.
// Block per (b,y) row; smem table T[r][c] = Qpad[y+r][c] (13 x 204 floats).
// Pattern of smem offsets repeats every 16 x positions (16*2401 = 38416 elems
// = 9604 float4 chunks); per-chunk 4 ushort offsets precomputed once.

#define GP_ROWS   204
#define GP_PITCH  208
#define T_ROWS    13
#define T_COLS    208
#define NT        512
#define NCHUNKS   9604           // float4 chunks per 38416-elem (16-x) region
#define ROW_ELEMS 460992         // 192 * 2401 floats per (b,y) row
#define XG_STRIDE 9604           // float4 stride between x-groups (38416/4)

__device__ __align__(16) float  g_padf[2][GP_ROWS][GP_PITCH];
__device__ __align__(8)  ushort4 g_desc[NCHUNKS];

// ---------------------------------------------------------------- prep kernels

__global__ void zero_pad_k() {
    int i = blockIdx.x * blockDim.x + threadIdx.x;
    float* p = (float*)g_padf;
    if (i < (int)(sizeof(g_padf) / 4)) p[i] = 0.0f;
}

__global__ void fill_k(const float* __restrict__ in) {
    int i = blockIdx.x * blockDim.x + threadIdx.x;     // 2*192*192 = 73728
    if (i >= 2 * 192 * 192) return;
    int b = i / (192 * 192);
    int r = (i / 192) % 192;
    int c = i % 192;
    unsigned int v = __float2uint_rz(in[i]);           // uint8 trunc, exact
    g_padf[b][6 + r][6 + c] = (float)v;
}

// Per-chunk descriptors: chunk u covers elements [4u, 4u+4) of a 38416-elem
// region (16 consecutive x). Element e: xi=e/2401 (x within group),
// rr=e%2401 -> w=rr/49 (wy,wx), p=rr%49 (ty,tx); smem offset
// = (wy+ty)*T_COLS + (xi+wx+tx); runtime adds 16*xg per x-group.
__global__ void desc_k() {
    int u = blockIdx.x * blockDim.x + threadIdx.x;
    if (u >= NCHUNKS) return;
    unsigned short off[4];
#pragma unroll
    for (int j = 0; j < 4; j++) {
        int e  = 4 * u + j;
        int xi = e / 2401;
        int rr = e - xi * 2401;
        int w  = rr / 49;
        int p  = rr - w * 49;
        int wy = w / 7, wx = w - wy * 7;
        int ty = p / 7, tx = p - ty * 7;
        off[j] = (unsigned short)((wy + ty) * T_COLS + (xi + wx + tx));
    }
    g_desc[u] = make_ushort4(off[0], off[1], off[2], off[3]);
}

// ---------------------------------------------------------------- main kernel

__global__ __launch_bounds__(NT) void main_k(float* __restrict__ out) {
    __shared__ float Tsh[T_ROWS * T_COLS];

    int rowid = blockIdx.x;              // 0..383 = b*192 + y
    int b   = rowid / 192;
    int y   = rowid - b * 192;
    int tid = threadIdx.x;

    // Build T table: Tsh[r*208 + c] = g_padf[b][y+r][c], c in [0,204)
    for (int idx = tid; idx < T_ROWS * 204; idx += NT) {
        int r = idx / 204;
        int c = idx - r * 204;
        Tsh[r * T_COLS + c] = g_padf[b][y + r][c];
    }
    __syncthreads();

    float* rowout = out + (size_t)rowid * ROW_ELEMS;

#pragma unroll 1
    for (int k = 0; k < (NCHUNKS + NT - 1) / NT; k++) {
        int u = tid + k * NT;
        if (u >= NCHUNKS) break;
        ushort4 d = g_desc[u];

        float4* gp = (float4*)(rowout + 4 * (size_t)u);

#pragma unroll
        for (int xg = 0; xg < 12; xg++) { // 12 x-groups of 16 x (192 total)
            int st = xg * 16;             // +16 smem columns per x-group
            float4 v;
            v.x = Tsh[d.x + st];
            v.y = Tsh[d.y + st];
            v.z = Tsh[d.z + st];
            v.w = Tsh[d.w + st];
            gp[(size_t)xg * XG_STRIDE] = v;  // stride 38416 floats, coalesced
        }
    }
}

// ---------------------------------------------------------------- launcher

extern "C" void kernel_launch(void* const* d_in, const int* in_sizes, int n_in,
                              void* d_out, int out_size) {
    const float* in = (const float*)d_in[0];
    // d_in[1] = search_range (fixed at 3: cv=7, offset=0 baked into desc_k)

    int zwords = (int)(sizeof(g_padf) / 4);
    zero_pad_k<<<(zwords + 255) / 256, 256>>>();
    fill_k<<<(2 * 192 * 192 + 255) / 256, 256>>>(in);
    desc_k<<<(NCHUNKS + 255) / 256, 256>>>();
    main_k<<<384, NT>>>((float*)d_out);
}

// round 3
// speedup vs baseline: 1.1117x; 1.1117x over previous
#include <cuda_runtime.h>
#include <stdint.h>

// ExtractSearchWindows: out[b,y,x, wy*7+wx, ty*7+tx] = Qpad[b][y+wy+ty][x+wx+tx]
// Qpad = zero-padded (pad=6) image, values = trunc(input) in [0,255). Output f32.
//
// 708 MB f32 stores, 294 KB input -> pure store-BW problem.
// Block per (b,y,slice): smem table T[r][c] = Qpad[y+r][c] (13 x 204 floats),
// slice covers 2401 of the 9604 float4 chunks of the 16-x periodic pattern.
// Per-chunk 4 ushort smem offsets precomputed once (76.8 KB, L2-resident).

#define GP_ROWS   204
#define GP_PITCH  208
#define T_ROWS    13
#define T_COLS    208
#define NT        512
#define NCHUNKS   9604           // float4 chunks per 38416-elem (16-x) region
#define SLICE     2401           // chunks per block (4 slices)
#define ROW_ELEMS 460992         // 192 * 2401 floats per (b,y) row
#define XG_STRIDE 9604           // float4 stride between x-groups (38416/4)

__device__ __align__(16) float  g_padf[2][GP_ROWS][GP_PITCH];
__device__ __align__(8)  ushort4 g_desc[NCHUNKS];

// ---------------------------------------------------------------- prep kernels

__global__ void zero_pad_k() {
    int i = blockIdx.x * blockDim.x + threadIdx.x;
    float* p = (float*)g_padf;
    if (i < (int)(sizeof(g_padf) / 4)) p[i] = 0.0f;
}

__global__ void fill_k(const float* __restrict__ in) {
    int i = blockIdx.x * blockDim.x + threadIdx.x;     // 2*192*192 = 73728
    if (i >= 2 * 192 * 192) return;
    int b = i / (192 * 192);
    int r = (i / 192) % 192;
    int c = i % 192;
    unsigned int v = __float2uint_rz(in[i]);           // uint8 trunc, exact
    g_padf[b][6 + r][6 + c] = (float)v;
}

// Per-chunk descriptors: chunk u covers elements [4u, 4u+4) of a 38416-elem
// region (16 consecutive x). Element e: xi=e/2401, rr=e%2401 -> w=rr/49,
// p=rr%49; smem offset = (wy+ty)*T_COLS + (xi+wx+tx); runtime adds 16*xg.
__global__ void desc_k() {
    int u = blockIdx.x * blockDim.x + threadIdx.x;
    if (u >= NCHUNKS) return;
    unsigned short off[4];
#pragma unroll
    for (int j = 0; j < 4; j++) {
        int e  = 4 * u + j;
        int xi = e / 2401;
        int rr = e - xi * 2401;
        int w  = rr / 49;
        int p  = rr - w * 49;
        int wy = w / 7, wx = w - wy * 7;
        int ty = p / 7, tx = p - ty * 7;
        off[j] = (unsigned short)((wy + ty) * T_COLS + (xi + wx + tx));
    }
    g_desc[u] = make_ushort4(off[0], off[1], off[2], off[3]);
}

// ---------------------------------------------------------------- main kernel

__global__ __launch_bounds__(NT) void main_k(float* __restrict__ out) {
    __shared__ float Tsh[T_ROWS * T_COLS];

    int rowid = blockIdx.x;              // 0..383 = b*192 + y
    int slice = blockIdx.y;              // 0..3
    int b   = rowid / 192;
    int y   = rowid - b * 192;
    int tid = threadIdx.x;

    // Build T table: Tsh[r*208 + c] = g_padf[b][y+r][c], c in [0,204)
    for (int idx = tid; idx < T_ROWS * 204; idx += NT) {
        int r = idx / 204;
        int c = idx - r * 204;
        Tsh[r * T_COLS + c] = g_padf[b][y + r][c];
    }
    __syncthreads();

    float* rowout = out + (size_t)rowid * ROW_ELEMS;

    int ubase = slice * SLICE;
    int uend  = ubase + SLICE;

#pragma unroll 1
    for (int u = ubase + tid; u < uend; u += NT) {
        ushort4 d = g_desc[u];

        float4* gp = (float4*)(rowout + 4 * (size_t)u);

#pragma unroll
        for (int xg = 0; xg < 12; xg++) { // 12 x-groups of 16 x (192 total)
            int st = xg * 16;             // +16 smem columns per x-group
            float4 v;
            v.x = Tsh[d.x + st];
            v.y = Tsh[d.y + st];
            v.z = Tsh[d.z + st];
            v.w = Tsh[d.w + st];
            __stcs(gp + (size_t)xg * XG_STRIDE, v);  // streaming store, coalesced
        }
    }
}

// ---------------------------------------------------------------- launcher

extern "C" void kernel_launch(void* const* d_in, const int* in_sizes, int n_in,
                              void* d_out, int out_size) {
    const float* in = (const float*)d_in[0];
    // d_in[1] = search_range (fixed at 3: cv=7, offset=0 baked into desc_k)

    int zwords = (int)(sizeof(g_padf) / 4);
    zero_pad_k<<<(zwords + 255) / 256, 256>>>();
    fill_k<<<(2 * 192 * 192 + 255) / 256, 256>>>(in);
    desc_k<<<(NCHUNKS + 255) / 256, 256>>>();
    dim3 grid(384, 4);
    main_k<<<grid, NT>>>((float*)d_out);
}

// round 4
// speedup vs baseline: 1.2114x; 1.0896x over previous
#include <cuda_runtime.h>
#include <stdint.h>

// ExtractSearchWindows: out[b,y,x, wy*7+wx, ty*7+tx] = Qpad[b][y+wy+ty][x+wx+tx]
// Qpad = zero-padded (pad=6) image, values = trunc(input) in [0,255). Output f32.
//
// 708 MB f32 stores -> pure store-BW problem. Block per (b,y,uslice):
// smem row table T[13][208] + 343 per-chunk descriptors; block covers
// 343 float4 chunks x 12 x-groups, retiled as 343x6 32B units (u-major
// lane map keeps stores/desc reads coalesced). grid(384,28) -> W=18.16
// waves of 592 resident blocks -> 95.6% tail efficiency.

#define GP_ROWS   204
#define GP_PITCH  208
#define T_ROWS    13
#define T_COLS    208
#define NT        512
#define NCHUNKS   9604           // float4 chunks per 38416-elem (16-x) region
#define SLICE     343            // chunks per block (28 slices)
#define NUNITS    (SLICE * 6)    // 2058 (u, xg-pair) units per block
#define ROW_ELEMS 460992         // 192 * 2401 floats per (b,y) row
#define XG_STRIDE 9604           // float4 stride between x-groups (38416/4)

__device__ __align__(16) float  g_padf[2][GP_ROWS][GP_PITCH];
__device__ __align__(8)  ushort4 g_desc[NCHUNKS];

// ---------------------------------------------------------------- prep kernels

// Fill entire padded array (zeros + truncated interior) in one pass.
__global__ void fill_k(const float* __restrict__ in) {
    int i = blockIdx.x * blockDim.x + threadIdx.x;   // 2*204*208 = 84864
    if (i >= 2 * GP_ROWS * GP_PITCH) return;
    int b  = i / (GP_ROWS * GP_PITCH);
    int r  = (i / GP_PITCH) % GP_ROWS;
    int c  = i % GP_PITCH;
    float v = 0.0f;
    if (r >= 6 && r < 198 && c >= 6 && c < 198) {
        unsigned int q = __float2uint_rz(in[(b * 192 + (r - 6)) * 192 + (c - 6)]);
        v = (float)q;
    }
    g_padf[b][r][c] = v;
}

// Per-chunk descriptors: chunk u covers elements [4u, 4u+4) of a 38416-elem
// region (16 consecutive x). Element e: xi=e/2401, rr=e%2401 -> w=rr/49,
// p=rr%49; smem offset = (wy+ty)*T_COLS + (xi+wx+tx); runtime adds 16*xg.
__global__ void desc_k() {
    int u = blockIdx.x * blockDim.x + threadIdx.x;
    if (u >= NCHUNKS) return;
    unsigned short off[4];
#pragma unroll
    for (int j = 0; j < 4; j++) {
        int e  = 4 * u + j;
        int xi = e / 2401;
        int rr = e - xi * 2401;
        int w  = rr / 49;
        int p  = rr - w * 49;
        int wy = w / 7, wx = w - wy * 7;
        int ty = p / 7, tx = p - ty * 7;
        off[j] = (unsigned short)((wy + ty) * T_COLS + (xi + wx + tx));
    }
    g_desc[u] = make_ushort4(off[0], off[1], off[2], off[3]);
}

// ---------------------------------------------------------------- main kernel

__global__ __launch_bounds__(NT) void main_k(float* __restrict__ out) {
    __shared__ float   Tsh[T_ROWS * T_COLS];
    __shared__ ushort4 Dsh[SLICE];

    int rowid = blockIdx.x;              // 0..383 = b*192 + y
    int usl   = blockIdx.y;              // 0..27
    int b   = rowid / 192;
    int y   = rowid - b * 192;
    int tid = threadIdx.x;
    int ubase = usl * SLICE;

    // Row table: Tsh[r*208 + c] = g_padf[b][y+r][c], c in [0,204)
    for (int idx = tid; idx < T_ROWS * 204; idx += NT) {
        int r = idx / 204;
        int c = idx - r * 204;
        Tsh[r * T_COLS + c] = g_padf[b][y + r][c];
    }
    // Descriptor slice into smem (reused 6x per chunk)
    if (tid < SLICE) Dsh[tid] = g_desc[ubase + tid];
    __syncthreads();

    float4* rowout4 = (float4*)(out + (size_t)rowid * ROW_ELEMS);

#pragma unroll 1
    for (int idx = tid; idx < NUNITS; idx += NT) {
        int xgp = idx / SLICE;           // 0..5 (pair of x-groups)
        int uu  = idx - xgp * SLICE;     // 0..342, u-major: lanes coalesced
        ushort4 d = Dsh[uu];
        float4* gp = rowout4 + (ubase + uu);

        int xg0 = 2 * xgp;
#pragma unroll
        for (int j = 0; j < 2; j++) {
            int st = (xg0 + j) * 16;     // +16 smem columns per x-group
            float4 v;
            v.x = Tsh[d.x + st];
            v.y = Tsh[d.y + st];
            v.z = Tsh[d.z + st];
            v.w = Tsh[d.w + st];
            __stcs(gp + (size_t)(xg0 + j) * XG_STRIDE, v);
        }
    }
}

// ---------------------------------------------------------------- launcher

extern "C" void kernel_launch(void* const* d_in, const int* in_sizes, int n_in,
                              void* d_out, int out_size) {
    const float* in = (const float*)d_in[0];
    // d_in[1] = search_range (fixed at 3: cv=7, offset=0 baked into desc_k)

    fill_k<<<(2 * GP_ROWS * GP_PITCH + 255) / 256, 256>>>(in);
    desc_k<<<(NCHUNKS + 255) / 256, 256>>>();
    dim3 grid(384, 28);
    main_k<<<grid, NT>>>((float*)d_out);
}

// round 5
// speedup vs baseline: 1.2464x; 1.0289x over previous
#include <cuda_runtime.h>
#include <stdint.h>

// ExtractSearchWindows: out[b,y,x, wy*7+wx, ty*7+tx] = Qpad[b][y+wy+ty][x+wx+tx]
// Qpad = zero-padded (pad=6) image, values = trunc(input) in [0,255). Output f32.
//
// 708 MB f32 stores -> pure store-BW problem. SINGLE kernel launch:
// each block (b,y,uslice) builds its 13x204 row table straight from the
// L2-resident input (bounds-predicated pad+trunc) and computes its 343
// chunk descriptors in-block, then streams 343 float4 chunks x 12 x-groups
// as 343x6 32B units (u-major lane map keeps stores coalesced).
// grid(384,28) -> W = 384*28/592 = 18.16 waves -> 95.6% tail efficiency.

#define T_ROWS    13
#define T_COLS    208
#define NT        512
#define SLICE     343            // float4 chunks per block (28 slices x 343 = 9604)
#define NUNITS    (SLICE * 6)    // 2058 (u, xg-pair) units per block
#define ROW_ELEMS 460992         // 192 * 2401 floats per (b,y) row
#define XG_STRIDE 9604           // float4 stride between x-groups (38416/4)

__global__ __launch_bounds__(NT) void main_k(const float* __restrict__ in,
                                             float* __restrict__ out) {
    __shared__ float   Tsh[T_ROWS * T_COLS];
    __shared__ ushort4 Dsh[SLICE];

    int rowid = blockIdx.x;              // 0..383 = b*192 + y
    int usl   = blockIdx.y;              // 0..27
    int b   = rowid / 192;
    int y   = rowid - b * 192;
    int tid = threadIdx.x;
    int ubase = usl * SLICE;

    // ---- Prologue A: row table directly from input (pad=6, trunc-to-u8) ----
    // Tsh[r*208 + c] = Qpad[b][y+r][c] for r in [0,13), c in [0,204)
    const float* inb = in + (size_t)b * 192 * 192;
    for (int idx = tid; idx < T_ROWS * 204; idx += NT) {
        int r = idx / 204;
        int c = idx - r * 204;
        int gr = y + r - 6;              // global image row
        int gc = c - 6;                  // global image col
        float v = 0.0f;
        if ((unsigned)gr < 192u && (unsigned)gc < 192u)
            v = (float)__float2uint_rz(inb[gr * 192 + gc]);
        Tsh[r * T_COLS + c] = v;
    }

    // ---- Prologue B: per-chunk descriptors for this slice, in-block ----
    // Chunk u covers elements [4u,4u+4) of the 38416-elem 16-x region.
    // Element e: xi=e/2401, rr=e%2401 -> w=rr/49 (wy,wx), p=rr%49 (ty,tx);
    // smem offset = (wy+ty)*T_COLS + (xi+wx+tx); runtime adds 16*xg.
    if (tid < SLICE) {
        int u = ubase + tid;
        unsigned short off[4];
#pragma unroll
        for (int j = 0; j < 4; j++) {
            int e  = 4 * u + j;
            int xi = e / 2401;
            int rr = e - xi * 2401;
            int w  = rr / 49;
            int p  = rr - w * 49;
            int wy = w / 7, wx = w - wy * 7;
            int ty = p / 7, tx = p - ty * 7;
            off[j] = (unsigned short)((wy + ty) * T_COLS + (xi + wx + tx));
        }
        Dsh[tid] = make_ushort4(off[0], off[1], off[2], off[3]);
    }
    __syncthreads();

    // ---- Main store stream ----
    float4* rowout4 = (float4*)(out + (size_t)rowid * ROW_ELEMS);

#pragma unroll 1
    for (int idx = tid; idx < NUNITS; idx += NT) {
        int xgp = idx / SLICE;           // 0..5 (pair of x-groups)
        int uu  = idx - xgp * SLICE;     // 0..342, u-major: lanes coalesced
        ushort4 d = Dsh[uu];
        float4* gp = rowout4 + (ubase + uu);

        int xg0 = 2 * xgp;
#pragma unroll
        for (int j = 0; j < 2; j++) {
            int st = (xg0 + j) * 16;     // +16 smem columns per x-group
            float4 v;
            v.x = Tsh[d.x + st];
            v.y = Tsh[d.y + st];
            v.z = Tsh[d.z + st];
            v.w = Tsh[d.w + st];
            __stcs(gp + (size_t)(xg0 + j) * XG_STRIDE, v);
        }
    }
}

// ---------------------------------------------------------------- launcher

extern "C" void kernel_launch(void* const* d_in, const int* in_sizes, int n_in,
                              void* d_out, int out_size) {
    const float* in = (const float*)d_in[0];
    // d_in[1] = search_range (fixed at 3: cv=7, offset=0 baked into descriptors)

    dim3 grid(384, 28);
    main_k<<<grid, NT>>>(in, (float*)d_out);
}